// round 5
// baseline (speedup 1.0000x reference)
#include <cuda_runtime.h>
#include <cuda_bf16.h>
#include <cstdint>

#define B_ 8
#define N_ 2500
#define E_ 100
#define F_ 50
#define Y_ 8922
#define KS 9

#define YT 128          // y per CTA
#define NC 128          // n per chunk
#define NCHUNK 20
#define YTILES 70       // ceil(8922/128)

typedef unsigned long long ull;

// ---------------- scratch (device globals) ----------------
__device__ float g_wt2[KS * E_ * F_];          // conv weights [k][e][f]
__device__ uint4 g_hh[B_ * N_ * 8];            // h hi bf16 rows [b*n][64f] (128B rows)
__device__ uint4 g_hl[B_ * N_ * 8];            // h lo bf16 rows
__device__ float g_loss;

// ---------------- packed f32x2 helpers (k1) ----------------
__device__ __forceinline__ float2 unpack2(ull v) {
    float2 r; asm("mov.b64 {%0, %1}, %2;" : "=f"(r.x), "=f"(r.y) : "l"(v)); return r;
}
__device__ __forceinline__ ull pack2(float a, float b) {
    ull r; asm("mov.b64 %0, {%1, %2};" : "=l"(r) : "f"(a), "f"(b)); return r;
}
__device__ __forceinline__ ull fma2(ull a, ull b, ull c) {
    ull d; asm("fma.rn.f32x2 %0, %1, %2, %3;" : "=l"(d) : "l"(a), "l"(b), "l"(c)); return d;
}

// ---------------- mma.sync bf16 (sm_80 baseline PTX; tensor pipe) ----------------
__device__ __forceinline__ void mma_bf16(float* d, const uint32_t* a, uint32_t b0, uint32_t b1) {
    asm volatile("mma.sync.aligned.m16n8k16.row.col.f32.bf16.bf16.f32 "
        "{%0,%1,%2,%3}, {%4,%5,%6,%7}, {%8,%9}, {%0,%1,%2,%3};"
        : "+f"(d[0]), "+f"(d[1]), "+f"(d[2]), "+f"(d[3])
        : "r"(a[0]), "r"(a[1]), "r"(a[2]), "r"(a[3]), "r"(b0), "r"(b1));
}

__device__ __forceinline__ void split2(float v0, float v1, uint32_t& hw, uint32_t& lw) {
    __nv_bfloat16 h0 = __float2bfloat16(v0);
    __nv_bfloat16 h1 = __float2bfloat16(v1);
    __nv_bfloat16 l0 = __float2bfloat16(v0 - __bfloat162float(h0));
    __nv_bfloat16 l1 = __float2bfloat16(v1 - __bfloat162float(h1));
    hw = (uint32_t)*(unsigned short*)&h0 | ((uint32_t)*(unsigned short*)&h1 << 16);
    lw = (uint32_t)*(unsigned short*)&l0 | ((uint32_t)*(unsigned short*)&l1 << 16);
}

// ---------------- K0a / K0b ----------------
__global__ void k0a_zero() { g_loss = 0.f; }

__global__ void k0b_prep(const float* __restrict__ conv_w) {
    int i = blockIdx.x * blockDim.x + threadIdx.x;
    if (i < F_ * E_ * KS) {
        int f = i / (E_ * KS);
        int r = i % (E_ * KS);
        int e = r / KS;
        int k = r % KS;
        g_wt2[(k * E_ + e) * F_ + f] = conv_w[i];
    }
}

// ---------------- K1: embedding + conv1d + tanh -> bf16 hi/lo rows ----------------
#define K1N 128
#define EP 101
#define WSP 26
__global__ __launch_bounds__(K1N) void k1_conv(
    const int* __restrict__ x,
    const float* __restrict__ embed_W,
    const float* __restrict__ conv_b)
{
    __shared__ float semb[(K1N + 8) * EP];
    __shared__ ull   ws[E_ * WSP];
    __shared__ int   stok[K1N + 8];

    int b   = blockIdx.y;
    int n0  = blockIdx.x * K1N;
    int tid = threadIdx.x;

    for (int r = tid; r < K1N + 8; r += K1N) {
        int n = n0 + r - 4;
        stok[r] = (n >= 0 && n < N_) ? x[b * N_ + n] : -1;
    }
    __syncthreads();

    const float4* embv = (const float4*)embed_W;
    for (int i = tid; i < (K1N + 8) * (E_ / 4); i += K1N) {
        int r  = i / (E_ / 4);
        int c4 = i % (E_ / 4);
        int tok = stok[r];
        float4 v = make_float4(0.f, 0.f, 0.f, 0.f);
        if (tok >= 0) v = embv[tok * (E_ / 4) + c4];
        float* dst = &semb[r * EP + c4 * 4];
        dst[0] = v.x; dst[1] = v.y; dst[2] = v.z; dst[3] = v.w;
    }

    ull acc[F_ / 2];
    #pragma unroll
    for (int fi = 0; fi < F_ / 2; fi++) acc[fi] = 0ull;

    for (int k = 0; k < KS; k++) {
        __syncthreads();
        const ull* wsrc = (const ull*)(g_wt2 + k * (E_ * F_));
        for (int i = tid; i < E_ * (F_ / 2); i += K1N) {
            int e = i / (F_ / 2), fi = i % (F_ / 2);
            ws[e * WSP + fi] = wsrc[i];
        }
        __syncthreads();

        const float* srow = &semb[(tid + k) * EP];
        #pragma unroll 4
        for (int e = 0; e < E_; e++) {
            ull hh = pack2(srow[e], srow[e]);
            const ull* w = &ws[e * WSP];
            #pragma unroll
            for (int fi = 0; fi < F_ / 2; fi++)
                acc[fi] = fma2(hh, w[fi], acc[fi]);
        }
    }

    int n = n0 + tid;
    if (n < N_) {
        float hv[64];
        #pragma unroll
        for (int fi = 0; fi < F_ / 2; fi++) {
            float2 a = unpack2(acc[fi]);
            hv[2 * fi]     = tanhf(a.x + conv_b[2 * fi]);
            hv[2 * fi + 1] = tanhf(a.y + conv_b[2 * fi + 1]);
        }
        #pragma unroll
        for (int j = F_; j < 64; j++) hv[j] = 0.f;

        size_t rb = (size_t)(b * N_ + n) * 8;
        #pragma unroll
        for (int s = 0; s < 8; s++) {
            uint32_t hw[4], lw[4];
            #pragma unroll
            for (int p = 0; p < 4; p++)
                split2(hv[s * 8 + p * 2], hv[s * 8 + p * 2 + 1], hw[p], lw[p]);
            g_hh[rb + s] = make_uint4(hw[0], hw[1], hw[2], hw[3]);
            g_hl[rb + s] = make_uint4(lw[0], lw[1], lw[2], lw[3]);
        }
    }
}

// ---------------- K2: fused attention via mma.sync ----------------
// CTA = (128 y, batch b). 8 warps: warp_m = wid&3 (32 y), warp_n = wid>>2 (64 n).
// Pass 1 processes each warp's 64-n window in two 32-n halves to cap registers
// (ds+dg = 64 live accumulators). Stats accumulate per-thread.
// Reduction arrays + pass-2 alpha stage OVERLAY the retired final-weights smem
// so 2 CTAs/SM fit (110.6 KB each).

#define RSTRIDE 144
#define S_UH 0
#define S_UL 18432
#define S_FH 36864       // post-pass1: reused for red arrays, then alpha stage
#define S_FL 55296
#define S_HH 73728
#define S_HL 92160
#define SMEM_K2 110592
#define S_RED S_FH       // [128][8] l + [128][8] a = 8192 B
#define S_LINV (S_FH + 8192)
#define STG_STRIDE 66    // stage: [128][66] f32 = 33792 B at S_FH

__global__ __launch_bounds__(256, 2) void k2_attn(
    const float* __restrict__ U_w,
    const float* __restrict__ finalW,
    const float* __restrict__ fbias,
    const float* __restrict__ target,
    float* __restrict__ out)
{
    extern __shared__ char smem[];
    int tid = threadIdx.x, wid = tid >> 5, lane = tid & 31;
    int gid = lane >> 2, tg = lane & 3;
    int warp_m = wid & 3, warp_n = wid >> 2;
    int b  = blockIdx.y;
    int y0 = blockIdx.x * YT;

    // ---- prologue: U (tid<128) / final (tid>=128) rows -> bf16 hi/lo ----
    {
        int yl = tid & 127;
        const float* src = (tid < 128) ? U_w : finalW;
        int roff = (tid < 128) ? S_UH : S_FH;
        int y = y0 + yl;
        float a[64];
        #pragma unroll
        for (int j = 0; j < 64; j++) a[j] = 0.f;
        if (y < Y_)
            for (int j = 0; j < F_; j++) a[j] = src[(size_t)y * F_ + j];
        #pragma unroll
        for (int s = 0; s < 8; s++) {
            uint32_t hw[4], lw[4];
            #pragma unroll
            for (int p = 0; p < 4; p++)
                split2(a[s * 8 + p * 2], a[s * 8 + p * 2 + 1], hw[p], lw[p]);
            *(uint4*)(smem + roff + yl * RSTRIDE + s * 16)         = make_uint4(hw[0], hw[1], hw[2], hw[3]);
            *(uint4*)(smem + roff + 18432 + yl * RSTRIDE + s * 16) = make_uint4(lw[0], lw[1], lw[2], lw[3]);
        }
    }

    float lacc[4], aacc[4];
    #pragma unroll
    for (int i = 0; i < 4; i++) { lacc[i] = 0.f; aacc[i] = 0.f; }

    // =================== PASS 1: stats ===================
    for (int c = 0; c < NCHUNK; c++) {
        int n0 = c * NC;

        __syncthreads();
        for (int idx = tid; idx < NC * 8; idx += 256) {
            int row = idx >> 3, seg = idx & 7;
            int n = n0 + row;
            uint4 vh = make_uint4(0, 0, 0, 0), vl = make_uint4(0, 0, 0, 0);
            if (n < N_) {
                size_t rbi = (size_t)(b * N_ + n) * 8 + seg;
                vh = g_hh[rbi]; vl = g_hl[rbi];
            }
            *(uint4*)(smem + S_HH + row * RSTRIDE + seg * 16) = vh;
            *(uint4*)(smem + S_HL + row * RSTRIDE + seg * 16) = vl;
        }
        __syncthreads();

        // two 32-n halves per warp: halves the live accumulator count
        #pragma unroll
        for (int nh = 0; nh < 2; nh++) {
            float ds[2][4][4], dg[2][4][4];
            #pragma unroll
            for (int mt = 0; mt < 2; mt++)
                #pragma unroll
                for (int nt = 0; nt < 4; nt++)
                    #pragma unroll
                    for (int j = 0; j < 4; j++) { ds[mt][nt][j] = 0.f; dg[mt][nt][j] = 0.f; }

            #pragma unroll
            for (int p = 0; p < 3; p++) {
                int aoffU = (p == 2) ? S_UL : S_UH;
                int aoffF = (p == 2) ? S_FL : S_FH;
                int boff  = (p == 1) ? S_HL : S_HH;
                #pragma unroll
                for (int ks = 0; ks < 4; ks++) {
                    int kb = ks * 32 + tg * 4;
                    uint32_t au[2][4], af[2][4];
                    #pragma unroll
                    for (int mt = 0; mt < 2; mt++) {
                        int r0 = (warp_m * 32 + mt * 16 + gid) * RSTRIDE;
                        au[mt][0] = *(const uint32_t*)(smem + aoffU + r0 + kb);
                        au[mt][1] = *(const uint32_t*)(smem + aoffU + r0 + 8 * RSTRIDE + kb);
                        au[mt][2] = *(const uint32_t*)(smem + aoffU + r0 + kb + 16);
                        au[mt][3] = *(const uint32_t*)(smem + aoffU + r0 + 8 * RSTRIDE + kb + 16);
                        af[mt][0] = *(const uint32_t*)(smem + aoffF + r0 + kb);
                        af[mt][1] = *(const uint32_t*)(smem + aoffF + r0 + 8 * RSTRIDE + kb);
                        af[mt][2] = *(const uint32_t*)(smem + aoffF + r0 + kb + 16);
                        af[mt][3] = *(const uint32_t*)(smem + aoffF + r0 + 8 * RSTRIDE + kb + 16);
                    }
                    #pragma unroll
                    for (int nt = 0; nt < 4; nt++) {
                        int br = (warp_n * 64 + nh * 32 + nt * 8 + gid) * RSTRIDE;
                        uint32_t b0 = *(const uint32_t*)(smem + boff + br + kb);
                        uint32_t b1 = *(const uint32_t*)(smem + boff + br + kb + 16);
                        mma_bf16(ds[0][nt], au[0], b0, b1);
                        mma_bf16(ds[1][nt], au[1], b0, b1);
                        mma_bf16(dg[0][nt], af[0], b0, b1);
                        mma_bf16(dg[1][nt], af[1], b0, b1);
                    }
                }
            }

            if (n0 + NC <= N_) {
                #pragma unroll
                for (int mt = 0; mt < 2; mt++)
                    #pragma unroll
                    for (int nt = 0; nt < 4; nt++)
                        #pragma unroll
                        for (int j = 0; j < 4; j++) {
                            float e = __expf(ds[mt][nt][j]);
                            lacc[mt * 2 + (j >> 1)] += e;
                            aacc[mt * 2 + (j >> 1)] += e * dg[mt][nt][j];
                        }
            } else {
                #pragma unroll
                for (int mt = 0; mt < 2; mt++)
                    #pragma unroll
                    for (int nt = 0; nt < 4; nt++)
                        #pragma unroll
                        for (int j = 0; j < 4; j++) {
                            int n = n0 + warp_n * 64 + nh * 32 + nt * 8 + tg * 2 + (j & 1);
                            float e = (n < N_) ? __expf(ds[mt][nt][j]) : 0.f;
                            lacc[mt * 2 + (j >> 1)] += e;
                            aacc[mt * 2 + (j >> 1)] += e * dg[mt][nt][j];
                        }
            }
        }
    }

    // ---- cross-warp stats reduction + logits/yhat/BCE (overlays F region) ----
    float* red_l = (float*)(smem + S_RED);
    float* red_a = red_l + 128 * 8;
    float* slinv = (float*)(smem + S_LINV);
    __syncthreads();
    #pragma unroll
    for (int i = 0; i < 4; i++) {
        int y_loc = warp_m * 32 + (i >> 1) * 16 + (i & 1) * 8 + gid;
        red_l[y_loc * 8 + warp_n * 4 + tg] = lacc[i];
        red_a[y_loc * 8 + warp_n * 4 + tg] = aacc[i];
    }
    __syncthreads();
    if (tid < 128) {
        float l = 0.f, a = 0.f;
        #pragma unroll
        for (int s = 0; s < 8; s++) { l += red_l[tid * 8 + s]; a += red_a[tid * 8 + s]; }
        float linv = 1.f / l;
        slinv[tid] = linv;
        int y = y0 + tid;
        float li = 0.f;
        if (y < Y_) {
            float logit = a * linv + fbias[y];
            float yh = 1.f / (1.f + __expf(-logit));
            out[b * Y_ + y] = yh;
            float t = target[b * Y_ + y];
            float p = fminf(fmaxf(yh, 1e-7f), 1.f - 1e-7f);
            li = -(t * logf(p) + (1.f - t) * log1pf(-p));
        }
        #pragma unroll
        for (int o = 16; o; o >>= 1) li += __shfl_xor_sync(0xffffffffu, li, o);
        if (lane == 0) atomicAdd(&g_loss, li);
    }
    __syncthreads();

    float linv4[4];
    #pragma unroll
    for (int i = 0; i < 4; i++)
        linv4[i] = slinv[warp_m * 32 + (i >> 1) * 16 + (i & 1) * 8 + gid];
    __syncthreads();   // linv4 read before stage overwrites the region

    // =================== PASS 2: alpha ===================
    float* stage = (float*)(smem + S_FH);   // [128][66] f32
    float* alpha = out + (B_ * Y_ + 1);

    for (int c = 0; c < NCHUNK; c++) {
        int n0 = c * NC;

        __syncthreads();
        for (int idx = tid; idx < NC * 8; idx += 256) {
            int row = idx >> 3, seg = idx & 7;
            int n = n0 + row;
            uint4 vh = make_uint4(0, 0, 0, 0), vl = make_uint4(0, 0, 0, 0);
            if (n < N_) {
                size_t rbi = (size_t)(b * N_ + n) * 8 + seg;
                vh = g_hh[rbi]; vl = g_hl[rbi];
            }
            *(uint4*)(smem + S_HH + row * RSTRIDE + seg * 16) = vh;
            *(uint4*)(smem + S_HL + row * RSTRIDE + seg * 16) = vl;
        }
        __syncthreads();

        float ds[2][8][4];
        #pragma unroll
        for (int mt = 0; mt < 2; mt++)
            #pragma unroll
            for (int nt = 0; nt < 8; nt++)
                #pragma unroll
                for (int j = 0; j < 4; j++) ds[mt][nt][j] = 0.f;

        #pragma unroll
        for (int p = 0; p < 3; p++) {
            int aoffU = (p == 2) ? S_UL : S_UH;
            int boff  = (p == 1) ? S_HL : S_HH;
            #pragma unroll
            for (int ks = 0; ks < 4; ks++) {
                int kb = ks * 32 + tg * 4;
                uint32_t au[2][4];
                #pragma unroll
                for (int mt = 0; mt < 2; mt++) {
                    int r0 = (warp_m * 32 + mt * 16 + gid) * RSTRIDE;
                    au[mt][0] = *(const uint32_t*)(smem + aoffU + r0 + kb);
                    au[mt][1] = *(const uint32_t*)(smem + aoffU + r0 + 8 * RSTRIDE + kb);
                    au[mt][2] = *(const uint32_t*)(smem + aoffU + r0 + kb + 16);
                    au[mt][3] = *(const uint32_t*)(smem + aoffU + r0 + 8 * RSTRIDE + kb + 16);
                }
                #pragma unroll
                for (int nt = 0; nt < 8; nt++) {
                    int br = (warp_n * 64 + nt * 8 + gid) * RSTRIDE;
                    uint32_t b0 = *(const uint32_t*)(smem + boff + br + kb);
                    uint32_t b1 = *(const uint32_t*)(smem + boff + br + kb + 16);
                    mma_bf16(ds[0][nt], au[0], b0, b1);
                    mma_bf16(ds[1][nt], au[1], b0, b1);
                }
            }
        }

        #pragma unroll
        for (int q = 0; q < 2; q++) {
            if (warp_n == q) {
                #pragma unroll
                for (int mt = 0; mt < 2; mt++)
                    #pragma unroll
                    for (int nt = 0; nt < 8; nt++)
                        #pragma unroll
                        for (int j = 0; j < 4; j++) {
                            int y_loc = warp_m * 32 + mt * 16 + (j >> 1) * 8 + gid;
                            int nc = nt * 8 + tg * 2 + (j & 1);
                            stage[y_loc * STG_STRIDE + nc] =
                                __expf(ds[mt][nt][j]) * linv4[mt * 2 + (j >> 1)];
                        }
            }
            __syncthreads();
            int nb = n0 + q * 64;
            #pragma unroll 4
            for (int r = 0; r < 16; r++) {
                int y = y0 + wid * 16 + r;
                if (y < Y_) {
                    size_t gb = (size_t)(b * Y_ + y) * N_ + nb;
                    const float* srow = &stage[(wid * 16 + r) * STG_STRIDE];
                    if (nb + lane < N_)      alpha[gb + lane]      = srow[lane];
                    if (nb + lane + 32 < N_) alpha[gb + lane + 32] = srow[lane + 32];
                }
            }
            __syncthreads();
        }
    }
}

// ---------------- K_fin ----------------
__global__ void k_fin(float* __restrict__ out) {
    out[B_ * Y_] = g_loss * (1.f / (float)(B_ * Y_));
}

extern "C" void kernel_launch(void* const* d_in, const int* in_sizes, int n_in,
                              void* d_out, int out_size) {
    const int*   x       = (const int*)  d_in[0];
    const float* target  = (const float*)d_in[1];
    const float* embed_W = (const float*)d_in[2];
    const float* conv_w  = (const float*)d_in[3];
    const float* conv_b  = (const float*)d_in[4];
    const float* U_w     = (const float*)d_in[5];
    const float* finalW  = (const float*)d_in[6];
    const float* fbias   = (const float*)d_in[7];
    float* out = (float*)d_out;

    k0a_zero<<<1, 1>>>();
    k0b_prep<<<(F_ * E_ * KS + 255) / 256, 256>>>(conv_w);
    k1_conv<<<dim3((N_ + K1N - 1) / K1N, B_), K1N>>>(x, embed_W, conv_b);

    cudaFuncSetAttribute(k2_attn, cudaFuncAttributeMaxDynamicSharedMemorySize, SMEM_K2);
    k2_attn<<<dim3(YTILES, B_), 256, SMEM_K2>>>(U_w, finalW, fbias, target, out);

    k_fin<<<1, 1>>>(out);
}

// round 6
// speedup vs baseline: 1.4931x; 1.4931x over previous
#include <cuda_runtime.h>
#include <cuda_bf16.h>
#include <cstdint>

#define B_ 8
#define N_ 2500
#define E_ 100
#define F_ 50
#define Y_ 8922
#define KS 9

#define YT 128          // y per CTA
#define NC 128          // n per chunk
#define NCHUNK 20
#define YTILES 70       // ceil(8922/128)

typedef unsigned long long ull;

// ---------------- scratch (device globals) ----------------
__device__ float g_wt2[KS * E_ * F_];          // conv weights [k][e][f]
__device__ uint4 g_hh[B_ * N_ * 8];            // h hi bf16 rows [b*n][64f] (128B rows)
__device__ uint4 g_hl[B_ * N_ * 8];            // h lo bf16 rows
__device__ float g_loss;

// ---------------- packed f32x2 helpers (k1) ----------------
__device__ __forceinline__ float2 unpack2(ull v) {
    float2 r; asm("mov.b64 {%0, %1}, %2;" : "=f"(r.x), "=f"(r.y) : "l"(v)); return r;
}
__device__ __forceinline__ ull pack2(float a, float b) {
    ull r; asm("mov.b64 %0, {%1, %2};" : "=l"(r) : "f"(a), "f"(b)); return r;
}
__device__ __forceinline__ ull fma2(ull a, ull b, ull c) {
    ull d; asm("fma.rn.f32x2 %0, %1, %2, %3;" : "=l"(d) : "l"(a), "l"(b), "l"(c)); return d;
}

// ---------------- tensor-core helpers (baseline PTX, compute_103-safe) ----------------
__device__ __forceinline__ void mma_bf16(float* d, const uint32_t* a, uint32_t b0, uint32_t b1) {
    asm volatile("mma.sync.aligned.m16n8k16.row.col.f32.bf16.bf16.f32 "
        "{%0,%1,%2,%3}, {%4,%5,%6,%7}, {%8,%9}, {%0,%1,%2,%3};"
        : "+f"(d[0]), "+f"(d[1]), "+f"(d[2]), "+f"(d[3])
        : "r"(a[0]), "r"(a[1]), "r"(a[2]), "r"(a[3]), "r"(b0), "r"(b1));
}
__device__ __forceinline__ void ldmx4(uint32_t* r, uint32_t addr) {
    asm volatile("ldmatrix.sync.aligned.m8n8.x4.shared.b16 {%0,%1,%2,%3}, [%4];"
        : "=r"(r[0]), "=r"(r[1]), "=r"(r[2]), "=r"(r[3]) : "r"(addr));
}
__device__ __forceinline__ void ldmx2(uint32_t* r, uint32_t addr) {
    asm volatile("ldmatrix.sync.aligned.m8n8.x2.shared.b16 {%0,%1}, [%2];"
        : "=r"(r[0]), "=r"(r[1]) : "r"(addr));
}
__device__ __forceinline__ uint32_t smem_u32(const void* p) {
    uint32_t a;
    asm("{ .reg .u64 t; cvta.to.shared.u64 t, %1; cvt.u32.u64 %0, t; }" : "=r"(a) : "l"(p));
    return a;
}
__device__ __forceinline__ void cp_async16(uint32_t saddr, const void* gaddr, uint32_t bytes) {
    asm volatile("cp.async.cg.shared.global [%0], [%1], 16, %2;"
        :: "r"(saddr), "l"(gaddr), "r"(bytes));
}
#define CP_COMMIT() asm volatile("cp.async.commit_group;")
#define CP_WAIT(n)  asm volatile("cp.async.wait_group %0;" :: "n"(n))

__device__ __forceinline__ void split2(float v0, float v1, uint32_t& hw, uint32_t& lw) {
    __nv_bfloat16 h0 = __float2bfloat16(v0);
    __nv_bfloat16 h1 = __float2bfloat16(v1);
    __nv_bfloat16 l0 = __float2bfloat16(v0 - __bfloat162float(h0));
    __nv_bfloat16 l1 = __float2bfloat16(v1 - __bfloat162float(h1));
    hw = (uint32_t)*(unsigned short*)&h0 | ((uint32_t)*(unsigned short*)&h1 << 16);
    lw = (uint32_t)*(unsigned short*)&l0 | ((uint32_t)*(unsigned short*)&l1 << 16);
}

// ---------------- K0a / K0b ----------------
__global__ void k0a_zero() { g_loss = 0.f; }

__global__ void k0b_prep(const float* __restrict__ conv_w) {
    int i = blockIdx.x * blockDim.x + threadIdx.x;
    if (i < F_ * E_ * KS) {
        int f = i / (E_ * KS);
        int r = i % (E_ * KS);
        int e = r / KS;
        int k = r % KS;
        g_wt2[(k * E_ + e) * F_ + f] = conv_w[i];
    }
}

// ---------------- K1: embedding + conv1d + tanh -> bf16 hi/lo rows ----------------
#define K1N 128
#define EP 101
#define WSP 26
__global__ __launch_bounds__(K1N) void k1_conv(
    const int* __restrict__ x,
    const float* __restrict__ embed_W,
    const float* __restrict__ conv_b)
{
    __shared__ float semb[(K1N + 8) * EP];
    __shared__ ull   ws[E_ * WSP];
    __shared__ int   stok[K1N + 8];

    int b   = blockIdx.y;
    int n0  = blockIdx.x * K1N;
    int tid = threadIdx.x;

    for (int r = tid; r < K1N + 8; r += K1N) {
        int n = n0 + r - 4;
        stok[r] = (n >= 0 && n < N_) ? x[b * N_ + n] : -1;
    }
    __syncthreads();

    const float4* embv = (const float4*)embed_W;
    for (int i = tid; i < (K1N + 8) * (E_ / 4); i += K1N) {
        int r  = i / (E_ / 4);
        int c4 = i % (E_ / 4);
        int tok = stok[r];
        float4 v = make_float4(0.f, 0.f, 0.f, 0.f);
        if (tok >= 0) v = embv[tok * (E_ / 4) + c4];
        float* dst = &semb[r * EP + c4 * 4];
        dst[0] = v.x; dst[1] = v.y; dst[2] = v.z; dst[3] = v.w;
    }

    ull acc[F_ / 2];
    #pragma unroll
    for (int fi = 0; fi < F_ / 2; fi++) acc[fi] = 0ull;

    for (int k = 0; k < KS; k++) {
        __syncthreads();
        const ull* wsrc = (const ull*)(g_wt2 + k * (E_ * F_));
        for (int i = tid; i < E_ * (F_ / 2); i += K1N) {
            int e = i / (F_ / 2), fi = i % (F_ / 2);
            ws[e * WSP + fi] = wsrc[i];
        }
        __syncthreads();

        const float* srow = &semb[(tid + k) * EP];
        #pragma unroll 4
        for (int e = 0; e < E_; e++) {
            ull hh = pack2(srow[e], srow[e]);
            const ull* w = &ws[e * WSP];
            #pragma unroll
            for (int fi = 0; fi < F_ / 2; fi++)
                acc[fi] = fma2(hh, w[fi], acc[fi]);
        }
    }

    int n = n0 + tid;
    if (n < N_) {
        float hv[64];
        #pragma unroll
        for (int fi = 0; fi < F_ / 2; fi++) {
            float2 a = unpack2(acc[fi]);
            hv[2 * fi]     = tanhf(a.x + conv_b[2 * fi]);
            hv[2 * fi + 1] = tanhf(a.y + conv_b[2 * fi + 1]);
        }
        #pragma unroll
        for (int j = F_; j < 64; j++) hv[j] = 0.f;

        size_t rb = (size_t)(b * N_ + n) * 8;
        #pragma unroll
        for (int s = 0; s < 8; s++) {
            uint32_t hw[4], lw[4];
            #pragma unroll
            for (int p = 0; p < 4; p++)
                split2(hv[s * 8 + p * 2], hv[s * 8 + p * 2 + 1], hw[p], lw[p]);
            g_hh[rb + s] = make_uint4(hw[0], hw[1], hw[2], hw[3]);
            g_hl[rb + s] = make_uint4(lw[0], lw[1], lw[2], lw[3]);
        }
    }
}

// ---------------- K2: fused attention, mma.sync + ldmatrix + cp.async ----------------
// Round-4 tiling (best so far): 8 warps, warp = 32y x 64n, full nt=8 accumulators.
// Fragment loads via ldmatrix (4x fewer shared-load instructions); h tiles
// double-buffered with cp.async so chunk c+1's global loads overlap chunk c MMA.

#define RSTRIDE 144
#define S_UH 0
#define S_UL 18432
#define S_FH 36864        // pass2: reused for red arrays / alpha stage
#define S_FL 55296
#define S_H0H 73728
#define S_H0L 92160
#define S_H1H 110592
#define S_H1L 129024
#define SMEM_K2 147456
#define S_RED S_FH
#define S_LINV (S_FH + 8192)
#define STG_STRIDE 66

__global__ __launch_bounds__(256) void k2_attn(
    const float* __restrict__ U_w,
    const float* __restrict__ finalW,
    const float* __restrict__ fbias,
    const float* __restrict__ target,
    float* __restrict__ out)
{
    extern __shared__ char smem[];
    uint32_t sbase = smem_u32(smem);
    int tid = threadIdx.x, wid = tid >> 5, lane = tid & 31;
    int gid = lane >> 2, tg = lane & 3;
    int warp_m = wid & 3, warp_n = wid >> 2;
    int b  = blockIdx.y;
    int y0 = blockIdx.x * YT;

    // per-lane ldmatrix base offsets
    uint32_t a_base = (uint32_t)((warp_m * 32 + (lane & 15)) * RSTRIDE + (lane >> 4) * 16);
    uint32_t b_base = (uint32_t)((warp_n * 64 + (lane & 7)) * RSTRIDE + ((lane >> 3) & 1) * 16);

    // ---- prologue: U (tid<128) / final (tid>=128) rows -> bf16 hi/lo ----
    {
        int yl = tid & 127;
        const float* src = (tid < 128) ? U_w : finalW;
        int roff = (tid < 128) ? S_UH : S_FH;
        int y = y0 + yl;
        float a[64];
        #pragma unroll
        for (int j = 0; j < 64; j++) a[j] = 0.f;
        if (y < Y_)
            for (int j = 0; j < F_; j++) a[j] = src[(size_t)y * F_ + j];
        #pragma unroll
        for (int s = 0; s < 8; s++) {
            uint32_t hw[4], lw[4];
            #pragma unroll
            for (int p = 0; p < 4; p++)
                split2(a[s * 8 + p * 2], a[s * 8 + p * 2 + 1], hw[p], lw[p]);
            *(uint4*)(smem + roff + yl * RSTRIDE + s * 16)         = make_uint4(hw[0], hw[1], hw[2], hw[3]);
            *(uint4*)(smem + roff + 18432 + yl * RSTRIDE + s * 16) = make_uint4(lw[0], lw[1], lw[2], lw[3]);
        }
    }

    const char* ghh = (const char*)g_hh;
    const char* ghl = (const char*)g_hl;
    const int hbufH[2] = { S_H0H, S_H1H };
    const int hbufL[2] = { S_H0L, S_H1L };

    // issue cp.async loads of chunk c into buffer bb (8 x 16B per thread)
    #define ISSUE_H(c, bb) do { \
        int _n0 = (c) * NC; \
        for (int idx = tid; idx < NC * 16; idx += 256) { \
            int seg = idx & 7, row = (idx >> 3) & 127, arr = idx >> 10; \
            int n = _n0 + row; \
            uint32_t bytes = (n < N_) ? 16u : 0u; \
            size_t go = ((size_t)(b * N_ + n) * 8 + seg) * 16; \
            const char* gp = arr ? (ghl + go) : (ghh + go); \
            uint32_t sa = sbase + (arr ? hbufL[bb] : hbufH[bb]) + row * RSTRIDE + seg * 16; \
            cp_async16(sa, gp, bytes); \
        } \
        CP_COMMIT(); \
    } while (0)

    float lacc[4], aacc[4];
    #pragma unroll
    for (int i = 0; i < 4; i++) { lacc[i] = 0.f; aacc[i] = 0.f; }

    // =================== PASS 1: stats ===================
    ISSUE_H(0, 0);
    for (int c = 0; c < NCHUNK; c++) {
        int n0 = c * NC;
        int bb = c & 1;
        if (c + 1 < NCHUNK) { ISSUE_H(c + 1, bb ^ 1); CP_WAIT(1); }
        else CP_WAIT(0);
        __syncthreads();

        uint32_t bh_base = sbase + hbufH[bb] + b_base;
        uint32_t bl_base = sbase + hbufL[bb] + b_base;

        float ds[2][8][4], dg[2][8][4];
        #pragma unroll
        for (int mt = 0; mt < 2; mt++)
            #pragma unroll
            for (int nt = 0; nt < 8; nt++)
                #pragma unroll
                for (int j = 0; j < 4; j++) { ds[mt][nt][j] = 0.f; dg[mt][nt][j] = 0.f; }

        #pragma unroll
        for (int p = 0; p < 3; p++) {
            uint32_t aU = sbase + ((p == 2) ? S_UL : S_UH) + a_base;
            uint32_t aF = sbase + ((p == 2) ? S_FL : S_FH) + a_base;
            uint32_t bB = (p == 1) ? bl_base : bh_base;
            #pragma unroll
            for (int ks = 0; ks < 4; ks++) {
                uint32_t au0[4], au1[4], af0[4], af1[4];
                ldmx4(au0, aU + ks * 32);
                ldmx4(au1, aU + ks * 32 + 16 * RSTRIDE);
                ldmx4(af0, aF + ks * 32);
                ldmx4(af1, aF + ks * 32 + 16 * RSTRIDE);
                #pragma unroll
                for (int nt = 0; nt < 8; nt++) {
                    uint32_t bf[2];
                    ldmx2(bf, bB + nt * 8 * RSTRIDE + ks * 32);
                    mma_bf16(ds[0][nt], au0, bf[0], bf[1]);
                    mma_bf16(ds[1][nt], au1, bf[0], bf[1]);
                    mma_bf16(dg[0][nt], af0, bf[0], bf[1]);
                    mma_bf16(dg[1][nt], af1, bf[0], bf[1]);
                }
            }
        }
        __syncthreads();   // frags consumed; next iter may overwrite this buffer

        if (n0 + NC <= N_) {
            #pragma unroll
            for (int mt = 0; mt < 2; mt++)
                #pragma unroll
                for (int nt = 0; nt < 8; nt++)
                    #pragma unroll
                    for (int j = 0; j < 4; j++) {
                        float e = __expf(ds[mt][nt][j]);
                        lacc[mt * 2 + (j >> 1)] += e;
                        aacc[mt * 2 + (j >> 1)] += e * dg[mt][nt][j];
                    }
        } else {
            #pragma unroll
            for (int mt = 0; mt < 2; mt++)
                #pragma unroll
                for (int nt = 0; nt < 8; nt++)
                    #pragma unroll
                    for (int j = 0; j < 4; j++) {
                        int n = n0 + warp_n * 64 + nt * 8 + tg * 2 + (j & 1);
                        float e = (n < N_) ? __expf(ds[mt][nt][j]) : 0.f;
                        lacc[mt * 2 + (j >> 1)] += e;
                        aacc[mt * 2 + (j >> 1)] += e * dg[mt][nt][j];
                    }
        }
    }

    // ---- cross-warp stats reduction + logits/yhat/BCE (F region retired) ----
    float* red_l = (float*)(smem + S_RED);
    float* red_a = red_l + 128 * 8;
    float* slinv = (float*)(smem + S_LINV);
    __syncthreads();
    #pragma unroll
    for (int i = 0; i < 4; i++) {
        int y_loc = warp_m * 32 + (i >> 1) * 16 + (i & 1) * 8 + gid;
        red_l[y_loc * 8 + warp_n * 4 + tg] = lacc[i];
        red_a[y_loc * 8 + warp_n * 4 + tg] = aacc[i];
    }
    __syncthreads();
    if (tid < 128) {
        float l = 0.f, a = 0.f;
        #pragma unroll
        for (int s = 0; s < 8; s++) { l += red_l[tid * 8 + s]; a += red_a[tid * 8 + s]; }
        float linv = 1.f / l;
        slinv[tid] = linv;
        int y = y0 + tid;
        float li = 0.f;
        if (y < Y_) {
            float logit = a * linv + fbias[y];
            float yh = 1.f / (1.f + __expf(-logit));
            out[b * Y_ + y] = yh;
            float t = target[b * Y_ + y];
            float p = fminf(fmaxf(yh, 1e-7f), 1.f - 1e-7f);
            li = -(t * logf(p) + (1.f - t) * log1pf(-p));
        }
        #pragma unroll
        for (int o = 16; o; o >>= 1) li += __shfl_xor_sync(0xffffffffu, li, o);
        if (lane == 0) atomicAdd(&g_loss, li);
    }
    __syncthreads();

    float linv4[4];
    #pragma unroll
    for (int i = 0; i < 4; i++)
        linv4[i] = slinv[warp_m * 32 + (i >> 1) * 16 + (i & 1) * 8 + gid];
    __syncthreads();   // linv read before stage overwrites region

    // =================== PASS 2: alpha ===================
    float* stage = (float*)(smem + S_FH);   // [128][66] f32
    float* alpha = out + (B_ * Y_ + 1);

    ISSUE_H(0, 0);
    for (int c = 0; c < NCHUNK; c++) {
        int n0 = c * NC;
        int bb = c & 1;
        if (c + 1 < NCHUNK) { ISSUE_H(c + 1, bb ^ 1); CP_WAIT(1); }
        else CP_WAIT(0);
        __syncthreads();

        uint32_t bh_base = sbase + hbufH[bb] + b_base;
        uint32_t bl_base = sbase + hbufL[bb] + b_base;

        float ds[2][8][4];
        #pragma unroll
        for (int mt = 0; mt < 2; mt++)
            #pragma unroll
            for (int nt = 0; nt < 8; nt++)
                #pragma unroll
                for (int j = 0; j < 4; j++) ds[mt][nt][j] = 0.f;

        #pragma unroll
        for (int p = 0; p < 3; p++) {
            uint32_t aU = sbase + ((p == 2) ? S_UL : S_UH) + a_base;
            uint32_t bB = (p == 1) ? bl_base : bh_base;
            #pragma unroll
            for (int ks = 0; ks < 4; ks++) {
                uint32_t au0[4], au1[4];
                ldmx4(au0, aU + ks * 32);
                ldmx4(au1, aU + ks * 32 + 16 * RSTRIDE);
                #pragma unroll
                for (int nt = 0; nt < 8; nt++) {
                    uint32_t bf[2];
                    ldmx2(bf, bB + nt * 8 * RSTRIDE + ks * 32);
                    mma_bf16(ds[0][nt], au0, bf[0], bf[1]);
                    mma_bf16(ds[1][nt], au1, bf[0], bf[1]);
                }
            }
        }
        __syncthreads();

        #pragma unroll
        for (int q = 0; q < 2; q++) {
            if (warp_n == q) {
                #pragma unroll
                for (int mt = 0; mt < 2; mt++)
                    #pragma unroll
                    for (int nt = 0; nt < 8; nt++)
                        #pragma unroll
                        for (int j = 0; j < 4; j++) {
                            int y_loc = warp_m * 32 + mt * 16 + (j >> 1) * 8 + gid;
                            int nc = nt * 8 + tg * 2 + (j & 1);
                            stage[y_loc * STG_STRIDE + nc] =
                                __expf(ds[mt][nt][j]) * linv4[mt * 2 + (j >> 1)];
                        }
            }
            __syncthreads();
            int nb = n0 + q * 64;
            #pragma unroll 4
            for (int r = 0; r < 16; r++) {
                int y = y0 + wid * 16 + r;
                if (y < Y_) {
                    size_t gb = (size_t)(b * Y_ + y) * N_ + nb;
                    const float* srow = &stage[(wid * 16 + r) * STG_STRIDE];
                    if (nb + lane < N_)      alpha[gb + lane]      = srow[lane];
                    if (nb + lane + 32 < N_) alpha[gb + lane + 32] = srow[lane + 32];
                }
            }
            __syncthreads();
        }
    }
    #undef ISSUE_H
}

// ---------------- K_fin ----------------
__global__ void k_fin(float* __restrict__ out) {
    out[B_ * Y_] = g_loss * (1.f / (float)(B_ * Y_));
}

extern "C" void kernel_launch(void* const* d_in, const int* in_sizes, int n_in,
                              void* d_out, int out_size) {
    const int*   x       = (const int*)  d_in[0];
    const float* target  = (const float*)d_in[1];
    const float* embed_W = (const float*)d_in[2];
    const float* conv_w  = (const float*)d_in[3];
    const float* conv_b  = (const float*)d_in[4];
    const float* U_w     = (const float*)d_in[5];
    const float* finalW  = (const float*)d_in[6];
    const float* fbias   = (const float*)d_in[7];
    float* out = (float*)d_out;

    k0a_zero<<<1, 1>>>();
    k0b_prep<<<(F_ * E_ * KS + 255) / 256, 256>>>(conv_w);
    k1_conv<<<dim3((N_ + K1N - 1) / K1N, B_), K1N>>>(x, embed_W, conv_b);

    cudaFuncSetAttribute(k2_attn, cudaFuncAttributeMaxDynamicSharedMemorySize, SMEM_K2);
    k2_attn<<<dim3(YTILES, B_), 256, SMEM_K2>>>(U_w, finalW, fbias, target, out);

    k_fin<<<1, 1>>>(out);
}